// round 13
// baseline (speedup 1.0000x reference)
#include <cuda_runtime.h>
#include <cuda_fp16.h>
#include <cstdint>

// ---------------- problem constants ----------------
#define BB    32
#define CIN   64
#define HH    128
#define WW    128
#define COUT  128
#define OHH   126
#define OWW   126

// ---------------- staging ----------------
// stage = (ki, ci-half): A = 3 kj x 128 co x 32 k halves (24576B),
//                        B = 132 px rows x 32 k halves (64B rows) = 8448B
#define A_BYTES 24576
#define B_BYTES 8448
#define STAGEB  (A_BYTES + B_BYTES)    // 33024
#define NSTAGE  6
#define SMEMB   (3 * STAGEB)           // 99072, triple-buffered

// static scratch (allocation-free rule); fp16 weights, k-interleaved
__device__ __align__(16) __half g_w2h[9*COUT*CIN];                  // [kk][co][perm(ci)]

// ---------------- helpers ----------------
__device__ __forceinline__ uint32_t smem_u32(const void* p) {
    uint32_t a;
    asm("{ .reg .u64 t; cvta.to.shared.u64 t, %1; cvt.u32.u64 %0, t; }" : "=r"(a) : "l"(p));
    return a;
}
__device__ __forceinline__ void cp16(uint32_t s, const void* g) {
    asm volatile("cp.async.cg.shared.global [%0], [%1], 16;" :: "r"(s), "l"(g));
}
// k-interleave within a 16-group: order [0,1,8,9, 2,3,10,11, 4,5,12,13, 6,7,14,15]
__device__ __forceinline__ int permk(int k) {
    return (((k >> 1) & 3) << 2) | (((k >> 3) & 1) << 1) | (k & 1);
}
__device__ __forceinline__ void mma_f16(float* d, const uint32_t* a, const uint32_t* b) {
    asm volatile(
        "mma.sync.aligned.m16n8k16.row.col.f32.f16.f16.f32 "
        "{%0,%1,%2,%3}, {%4,%5,%6,%7}, {%8,%9}, {%0,%1,%2,%3};"
        : "+f"(d[0]), "+f"(d[1]), "+f"(d[2]), "+f"(d[3])
        : "r"(a[0]), "r"(a[1]), "r"(a[2]), "r"(a[3]), "r"(b[0]), "r"(b[1]));
}

// ---------------- pre-pass: w[co][ci][3][3] -> g_w2h[kk][co][perm(ci)] ----------------
__global__ void wtrans_kernel(const float* __restrict__ w) {
    int idx = blockIdx.x * 256 + threadIdx.x;
    if (idx >= 9 * COUT * CIN) return;
    int ci = idx & 63; int t = idx >> 6; int co = t & 127; int kk = t >> 7;
    int q = (ci & ~15) | permk(ci & 15);
    g_w2h[((size_t)kk * COUT + co) * CIN + q] =
        __float2half_rn(w[((size_t)co * CIN + ci) * 9 + kk]);
}

// ---------------- fused activation ----------------
__device__ __forceinline__ float actf(float v, float bi, float mu) {
    float y = (v + bi) * mu;
    y = (y >= 0.f) ? y : 0.01f * y;
    float t = 0.7978845608028654f * fmaf(0.044715f * y, y * y, y);
    float a = fminf(fabsf(t), 14.f);
    float u = __expf(-2.f * a);                  // (0, 1]
    float th = __fdividef(1.f - u, 1.f + u);     // tanh(a)
    th = (t >= 0.f) ? th : -th;
    return 0.5f * y * (1.f + th);
}

// ---------------- main kernel: implicit GEMM via mma.sync f16 ----------------
// CTA = (oh, b). D[co=128][px=128]; 8 warps in 4(M) x 2(N), each 32x64.
// 6 stages (ki, ci-half), triple-buffered, one __syncthreads per stage.
// A (weights) via cp.async from fp16 scratch; B (x) read fp32 NCHW directly:
// LDG.128 -> cvt -> STS.16 into the same px-major rotated fp16 layout.
__global__ __launch_bounds__(256, 2)
void conv_mma_kernel(const float* __restrict__ x,
                     const float* __restrict__ bias, const float* __restrict__ mult,
                     float* __restrict__ out)
{
    extern __shared__ char sm[];
    const int tid = threadIdx.x;
    const int wid = tid >> 5, lid = tid & 31;
    const int wm  = wid >> 1, wn = wid & 1;
    const int g   = lid >> 2, c = lid & 3;
    const int oh  = blockIdx.x;
    const int b   = blockIdx.y;
    const uint32_t sb = smem_u32(sm);

    // B-loader per-thread constants: ci row + perm'd column slot
    const int ci_  = tid & 31;      // k within 32-chunk
    const int wq   = tid >> 5;      // float4 group base
    const int kp   = (ci_ & ~15) | permk(ci_ & 15);
    const int blkk = kp >> 3;
    const int kb   = (kp & 7) * 2;

    float acc[2][8][4];
#pragma unroll
    for (int mt = 0; mt < 2; mt++)
#pragma unroll
        for (int nt = 0; nt < 8; nt++)
#pragma unroll
            for (int i = 0; i < 4; i++) acc[mt][nt][i] = 0.f;

    // ---- A prefetch: 384 rows (kj*128+co) x 32 k halves, rotated 16B blocks ----
#define PREFA(S, BOFF) do {                                                     \
        const int ki_ = (S) >> 1, c2_ = (S) & 1;                                \
        const __half* wbase = g_w2h + (size_t)(ki_ * 3) * COUT * CIN + c2_ * 32;\
        const uint32_t sbase = sb + (BOFF);                                     \
        _Pragma("unroll")                                                       \
        for (int kq = 0; kq < 6; kq++) {                                        \
            int idx = tid + kq * 256;                                           \
            int r = idx >> 2, blk = idx & 3;                                    \
            cp16(sbase + r * 64 + ((blk + r) & 3) * 16,                         \
                 wbase + (size_t)r * CIN + blk * 8);                            \
        }                                                                       \
        asm volatile("cp.async.commit_group;" ::: "memory");                    \
    } while (0)

    // ---- B gmem load: 4x LDG.128 fp32 (this thread's ci row, px 4*(wq+8q)) ----
#define LDGB(S, REG) do {                                                       \
        const int ki_ = (S) >> 1, c2_ = (S) & 1;                                \
        const float* xr = x + ((size_t)(b * CIN + c2_ * 32 + ci_) * HH          \
                               + oh + ki_) * WW;                                \
        _Pragma("unroll")                                                       \
        for (int q = 0; q < 4; q++)                                             \
            (REG)[q] = *reinterpret_cast<const float4*>(xr + (wq + q * 8) * 4); \
    } while (0)

    // ---- B smem store: cvt fp32->fp16, scatter into px-major rotated layout ----
#define STSB(BOFF, REG) do {                                                    \
        const uint32_t bb = sb + (BOFF) + A_BYTES;                              \
        _Pragma("unroll")                                                       \
        for (int q = 0; q < 4; q++) {                                           \
            float f[4] = {(REG)[q].x, (REG)[q].y, (REG)[q].z, (REG)[q].w};      \
            _Pragma("unroll")                                                   \
            for (int j = 0; j < 4; j++) {                                       \
                int n = (wq + q * 8) * 4 + j;                                   \
                uint32_t ad = bb + n * 64 + ((blkk + n) & 3) * 16 + kb;         \
                unsigned short hv = __half_as_ushort(__float2half_rn(f[j]));    \
                asm volatile("st.shared.u16 [%0], %1;" :: "r"(ad), "h"(hv));    \
            }                                                                   \
        }                                                                       \
    } while (0)

    // ---- prologue: stages 0 and 1 ----
    PREFA(0, 0);
    PREFA(1, STAGEB);
    {
        float4 t0[4], t1[4];
        LDGB(0, t0); LDGB(1, t1);
        STSB(0, t0); STSB(STAGEB, t1);
    }

    int coff = 0;                 // buffer offset of stage s
    int poff = 2 * STAGEB;        // buffer offset of stage s+2
    float4 breg[4];
#pragma unroll 1
    for (int s = 0; s < NSTAGE; s++) {
        const bool more = (s + 2 < NSTAGE);
        if (more) LDGB(s + 2, breg);                 // issue early, consume late
        if (s < NSTAGE - 1) asm volatile("cp.async.wait_group 1;" ::: "memory");
        else                asm volatile("cp.async.wait_group 0;" ::: "memory");
        __syncthreads();
        if (more) PREFA(s + 2, poff);

        const uint32_t Ab = sb + coff;
        const uint32_t Bb = Ab + A_BYTES;
        const int s8 = (c & 1) * 8;

#pragma unroll
        for (int kj = 0; kj < 3; kj++) {
#pragma unroll
            for (int ks = 0; ks < 2; ks++) {
                const int blk = ks * 2 + (c >> 1);
                uint32_t af[2][4];
#pragma unroll
                for (int mt = 0; mt < 2; mt++) {
                    int r0 = kj * 128 + wm * 32 + mt * 16 + g;
                    uint32_t a0 = Ab + r0 * 64 + ((blk + r0) & 3) * 16 + s8;
                    uint32_t a1 = Ab + (r0 + 8) * 64 + ((blk + r0 + 8) & 3) * 16 + s8;
                    asm volatile("ld.shared.v2.b32 {%0,%1}, [%2];"
                                 : "=r"(af[mt][0]), "=r"(af[mt][2]) : "r"(a0));
                    asm volatile("ld.shared.v2.b32 {%0,%1}, [%2];"
                                 : "=r"(af[mt][1]), "=r"(af[mt][3]) : "r"(a1));
                }
                uint32_t bf[8][2];
#pragma unroll
                for (int nt = 0; nt < 8; nt++) {
                    int n = wn * 64 + nt * 8 + g + kj;
                    uint32_t a = Bb + n * 64 + ((blk + n) & 3) * 16 + s8;
                    asm volatile("ld.shared.v2.b32 {%0,%1}, [%2];"
                                 : "=r"(bf[nt][0]), "=r"(bf[nt][1]) : "r"(a));
                }
#pragma unroll
                for (int mt = 0; mt < 2; mt++)
#pragma unroll
                    for (int nt = 0; nt < 8; nt++)
                        mma_f16(acc[mt][nt], af[mt], bf[nt]);
            }
        }
        if (more) STSB(poff, breg);                  // fill stage s+2 B tile
        coff += STAGEB; if (coff == 3 * STAGEB) coff = 0;
        poff += STAGEB; if (poff == 3 * STAGEB) poff = 0;
    }

    // ---- epilogue: bias -> mult -> leaky -> GELU -> store ----
#pragma unroll
    for (int mt = 0; mt < 2; mt++) {
#pragma unroll
        for (int half = 0; half < 2; half++) {
            const int co = wm * 32 + mt * 16 + g + half * 8;
            const float bi = bias[co];
            const float mu = mult[co];
            float* op = out + (((size_t)b * COUT + co) * OHH + oh) * OWW;
#pragma unroll
            for (int nt = 0; nt < 8; nt++) {
                const int ow = wn * 64 + nt * 8 + 2 * c;
                if (ow + 1 < OWW) {
                    float f0 = actf(acc[mt][nt][half * 2 + 0], bi, mu);
                    float f1 = actf(acc[mt][nt][half * 2 + 1], bi, mu);
                    *reinterpret_cast<float2*>(op + ow) = make_float2(f0, f1);
                }
            }
        }
    }
}

// ---------------- launch ----------------
extern "C" void kernel_launch(void* const* d_in, const int* in_sizes, int n_in,
                              void* d_out, int out_size)
{
    const float* x    = (const float*)d_in[0];
    const float* w    = (const float*)d_in[1];
    const float* bias = (const float*)d_in[2];
    const float* mult = (const float*)d_in[3];
    float*       out  = (float*)d_out;

    cudaFuncSetAttribute(conv_mma_kernel,
                         cudaFuncAttributeMaxDynamicSharedMemorySize, SMEMB);

    wtrans_kernel<<<(9 * COUT * CIN + 255) / 256, 256>>>(w);
    conv_mma_kernel<<<dim3(OHH, BB), 256, SMEMB>>>(x, bias, mult, out);
}

// round 14
// speedup vs baseline: 1.0779x; 1.0779x over previous
#include <cuda_runtime.h>
#include <cuda_fp16.h>
#include <cstdint>

// ---------------- problem constants ----------------
#define BB    32
#define CIN   64
#define HH    128
#define WW    128
#define COUT  128
#define OHH   126
#define OWW   126

// ---------------- staging ----------------
// stage = (ki, ci-half): A = 3 kj x 128 co x 32 k halves (24576B),
//                        B = 130 px rows x 32 k halves (64B rows, 132 alloc = 8448B)
#define A_BYTES 24576
#define B_BYTES 8448
#define STAGEB  (A_BYTES + B_BYTES)    // 33024
#define NSTAGE  6
#define SMEMB   (3 * STAGEB)           // 99072, triple-buffered

// static scratch (allocation-free rule); fp16, k32-interleaved for v4 fragment loads
__device__ __align__(16) __half g_xTh[(size_t)BB*HH*WW*CIN + 8192]; // [b][h][w][perm(ci)]
__device__ __align__(16) __half g_w2h[9*COUT*CIN];                  // [kk][co][perm(ci)]

// ---------------- helpers ----------------
__device__ __forceinline__ uint32_t smem_u32(const void* p) {
    uint32_t a;
    asm("{ .reg .u64 t; cvta.to.shared.u64 t, %1; cvt.u32.u64 %0, t; }" : "=r"(a) : "l"(p));
    return a;
}
__device__ __forceinline__ void cp16(uint32_t s, const void* g) {
    asm volatile("cp.async.cg.shared.global [%0], [%1], 16;" :: "r"(s), "l"(g));
}
// k32 interleave: logical k = 16h + 8a + 2c + b  ->  phys = 8c + 4h + 2a + b.
// Thread c's 16B block (phys 8c..8c+7) = {a0,a2 pairs} for BOTH k16 groups.
__device__ __forceinline__ int perm32(int k) {
    int u = k & 15, h = k >> 4;
    int a = (u >> 3) & 1, b = u & 1, cc = (u >> 1) & 3;
    return cc * 8 + h * 4 + a * 2 + b;
}
__device__ __forceinline__ void mma_f16(float* d, const uint32_t* a, const uint32_t* b) {
    asm volatile(
        "mma.sync.aligned.m16n8k16.row.col.f32.f16.f16.f32 "
        "{%0,%1,%2,%3}, {%4,%5,%6,%7}, {%8,%9}, {%0,%1,%2,%3};"
        : "+f"(d[0]), "+f"(d[1]), "+f"(d[2]), "+f"(d[3])
        : "r"(a[0]), "r"(a[1]), "r"(a[2]), "r"(a[3]), "r"(b[0]), "r"(b[1]));
}

// ---------------- pre-pass: w[co][ci][3][3] -> g_w2h[kk][co][perm(ci)] ----------------
__global__ void wtrans_kernel(const float* __restrict__ w) {
    int idx = blockIdx.x * 256 + threadIdx.x;
    if (idx >= 9 * COUT * CIN) return;
    int ci = idx & 63; int t = idx >> 6; int co = t & 127; int kk = t >> 7;
    int q = (ci & 32) | perm32(ci & 31);
    g_w2h[((size_t)kk * COUT + co) * CIN + q] =
        __float2half_rn(w[((size_t)co * CIN + ci) * 9 + kk]);
}

// ---------------- pre-pass: x[b][ci][h][w] -> g_xTh[b][h][w][perm(ci)] ----------------
__global__ void xtrans_kernel(const float* __restrict__ x) {
    __shared__ float tile[32][33];
    int bh = blockIdx.z;                    // b*128 + h
    int c0 = blockIdx.y * 32;
    int w0 = blockIdx.x * 32;
    int b = bh >> 7, h = bh & 127;
    int tx = threadIdx.x, ty = threadIdx.y; // 32 x 8
    const float* xp = x + ((size_t)b * CIN) * HH * WW + (size_t)h * WW;
#pragma unroll
    for (int i = 0; i < 32; i += 8)
        tile[ty + i][tx] = xp[(size_t)(c0 + ty + i) * HH * WW + w0 + tx];
    __syncthreads();
    __half* xo = g_xTh + (((size_t)b * HH + h) * WW) * CIN;
    int ci = c0 + tx;
    int q = (ci & 32) | perm32(ci & 31);
#pragma unroll
    for (int i = 0; i < 32; i += 8)
        xo[(size_t)(w0 + ty + i) * CIN + q] = __float2half_rn(tile[tx][ty + i]);
}

// ---------------- fused activation ----------------
__device__ __forceinline__ float actf(float v, float bi, float mu) {
    float y = (v + bi) * mu;
    y = (y >= 0.f) ? y : 0.01f * y;
    float t = 0.7978845608028654f * fmaf(0.044715f * y, y * y, y);
    float a = fminf(fabsf(t), 14.f);
    float u = __expf(-2.f * a);                  // (0, 1]
    float th = __fdividef(1.f - u, 1.f + u);     // tanh(a)
    th = (t >= 0.f) ? th : -th;
    return 0.5f * y * (1.f + th);
}

// ---------------- main kernel: implicit GEMM via mma.sync f16 ----------------
// CTA = (oh, b). D[co=128][px=128]; 8 warps in 4(M) x 2(N), each 32x64.
// 6 stages (ki, ci-half), triple-buffered, ONE __syncthreads per stage.
// One LDS.128 per fragment row covers BOTH k16 steps (perm32 layout).
__global__ __launch_bounds__(256, 2)
void conv_mma_kernel(const float* __restrict__ bias, const float* __restrict__ mult,
                     float* __restrict__ out)
{
    extern __shared__ char sm[];
    const int tid = threadIdx.x;
    const int wid = tid >> 5, lid = tid & 31;
    const int wm  = wid >> 1, wn = wid & 1;
    const int g   = lid >> 2, c = lid & 3;
    const int oh  = blockIdx.x;
    const int b   = blockIdx.y;
    const uint32_t sb = smem_u32(sm);

    float acc[2][8][4];
#pragma unroll
    for (int mt = 0; mt < 2; mt++)
#pragma unroll
        for (int nt = 0; nt < 8; nt++)
#pragma unroll
            for (int i = 0; i < 4; i++) acc[mt][nt][i] = 0.f;

    // A rows r = kj*128 + co (384 rows), B rows p = 0..129.
    // 16B-block rotation (blk+row)&3; loader copies physical 16B blocks.
#define PREFETCH(S, BOFF) do {                                                  \
        const int ki_ = (S) >> 1, c2_ = (S) & 1;                                \
        const __half* wbase = g_w2h + (size_t)(ki_ * 3) * COUT * CIN + c2_ * 32;\
        const __half* xbase = g_xTh +                                           \
            (((size_t)b * HH + oh + ki_) * WW) * CIN + c2_ * 32;                \
        const uint32_t sbase = sb + (BOFF);                                     \
        _Pragma("unroll")                                                       \
        for (int kq = 0; kq < 9; kq++) {                                        \
            int idx = tid + kq * 256;                                           \
            if (idx < 1536) {                                                   \
                int r = idx >> 2, blk = idx & 3;                                \
                cp16(sbase + r * 64 + ((blk + r) & 3) * 16,                     \
                     wbase + (size_t)r * CIN + blk * 8);                        \
            } else if (idx < 2056) {                                            \
                int j = idx - 1536, p = j >> 2, blk = j & 3;                    \
                cp16(sbase + A_BYTES + p * 64 + ((blk + p) & 3) * 16,           \
                     xbase + (size_t)p * CIN + blk * 8);                        \
            }                                                                   \
        }                                                                       \
        asm volatile("cp.async.commit_group;" ::: "memory");                    \
    } while (0)

    PREFETCH(0, 0);
    PREFETCH(1, STAGEB);

    int coff = 0;                 // buffer offset of stage s
    int poff = 2 * STAGEB;        // buffer offset of stage s+2
#pragma unroll 1
    for (int s = 0; s < NSTAGE; s++) {
        if (s < NSTAGE - 1) asm volatile("cp.async.wait_group 1;" ::: "memory");
        else                asm volatile("cp.async.wait_group 0;" ::: "memory");
        __syncthreads();
        if (s + 2 < NSTAGE) PREFETCH(s + 2, poff);

        const uint32_t Ab = sb + coff;
        const uint32_t Bb = Ab + A_BYTES;

#pragma unroll
        for (int kj = 0; kj < 3; kj++) {
            // A fragments: one v4 per row; covers ks=0 and ks=1
            uint32_t al[2][4], ah[2][4];
#pragma unroll
            for (int mt = 0; mt < 2; mt++) {
                int r0 = kj * 128 + wm * 32 + mt * 16 + g;
                uint32_t ad0 = Ab + r0 * 64 + (((c + r0) & 3) << 4);
                uint32_t ad1 = Ab + (r0 + 8) * 64 + (((c + r0 + 8) & 3) << 4);
                asm volatile("ld.shared.v4.b32 {%0,%1,%2,%3}, [%4];"
                    : "=r"(al[mt][0]), "=r"(al[mt][1]), "=r"(al[mt][2]), "=r"(al[mt][3])
                    : "r"(ad0));
                asm volatile("ld.shared.v4.b32 {%0,%1,%2,%3}, [%4];"
                    : "=r"(ah[mt][0]), "=r"(ah[mt][1]), "=r"(ah[mt][2]), "=r"(ah[mt][3])
                    : "r"(ad1));
            }
            // B fragments: one v4 per nt; covers ks=0 and ks=1
            uint32_t bq[8][4];
#pragma unroll
            for (int nt = 0; nt < 8; nt++) {
                int n = wn * 64 + nt * 8 + g + kj;
                uint32_t ad = Bb + n * 64 + (((c + n) & 3) << 4);
                asm volatile("ld.shared.v4.b32 {%0,%1,%2,%3}, [%4];"
                    : "=r"(bq[nt][0]), "=r"(bq[nt][1]), "=r"(bq[nt][2]), "=r"(bq[nt][3])
                    : "r"(ad));
            }
#pragma unroll
            for (int ks = 0; ks < 2; ks++) {
#pragma unroll
                for (int mt = 0; mt < 2; mt++) {
                    uint32_t afr[4] = { al[mt][2*ks], ah[mt][2*ks],
                                        al[mt][2*ks+1], ah[mt][2*ks+1] };
#pragma unroll
                    for (int nt = 0; nt < 8; nt++) {
                        uint32_t bfr[2] = { bq[nt][2*ks], bq[nt][2*ks+1] };
                        mma_f16(acc[mt][nt], afr, bfr);
                    }
                }
            }
        }
        coff += STAGEB; if (coff == 3 * STAGEB) coff = 0;
        poff += STAGEB; if (poff == 3 * STAGEB) poff = 0;
    }

    // ---- epilogue: bias -> mult -> leaky -> GELU -> store ----
#pragma unroll
    for (int mt = 0; mt < 2; mt++) {
#pragma unroll
        for (int half = 0; half < 2; half++) {
            const int co = wm * 32 + mt * 16 + g + half * 8;
            const float bi = bias[co];
            const float mu = mult[co];
            float* op = out + (((size_t)b * COUT + co) * OHH + oh) * OWW;
#pragma unroll
            for (int nt = 0; nt < 8; nt++) {
                const int ow = wn * 64 + nt * 8 + 2 * c;
                if (ow + 1 < OWW) {
                    float f0 = actf(acc[mt][nt][half * 2 + 0], bi, mu);
                    float f1 = actf(acc[mt][nt][half * 2 + 1], bi, mu);
                    *reinterpret_cast<float2*>(op + ow) = make_float2(f0, f1);
                }
            }
        }
    }
}

// ---------------- launch ----------------
extern "C" void kernel_launch(void* const* d_in, const int* in_sizes, int n_in,
                              void* d_out, int out_size)
{
    const float* x    = (const float*)d_in[0];
    const float* w    = (const float*)d_in[1];
    const float* bias = (const float*)d_in[2];
    const float* mult = (const float*)d_in[3];
    float*       out  = (float*)d_out;

    cudaFuncSetAttribute(conv_mma_kernel,
                         cudaFuncAttributeMaxDynamicSharedMemorySize, SMEMB);

    wtrans_kernel<<<(9 * COUT * CIN + 255) / 256, 256>>>(w);
    xtrans_kernel<<<dim3(WW / 32, CIN / 32, BB * HH), dim3(32, 8)>>>(x);
    conv_mma_kernel<<<dim3(OHH, BB), 256, SMEMB>>>(bias, mult, out);
}